// round 8
// baseline (speedup 1.0000x reference)
#include <cuda_runtime.h>
#include <math_constants.h>

#define BATCH 262144
#define NLAYER 8
#define H 128
#define NSEG 129
#define BN_EPS 1e-5f
#define FLOW_EPS 1e-4f
#define NREP 4
#define NB 148
#define NT 1024

// ---------------- device scratch (no allocs allowed) ----------------
__device__ unsigned g_arrive = 0, g_release = 0;   // grid barrier (monotonic, replay-safe)
__device__ double g_sum[2][2];                     // [parity][s,q]
__device__ int    g_cntR[2][NREP][NSEG];
__device__ float  g_s1R[2][NREP][NSEG], g_s2R[2][NREP][NSEG];
__device__ __align__(16) float g_tab[NSEG * H * 2];   // level-1 table (A,B per m,j)
__device__ float  g_kink2[NSEG * H];                  // sorted level-2 kinks per segment
__device__ __align__(16) float4 g_EF[NSEG * NSEG];    // (E0,F0,E1,F1) per (m, rank)
__device__ float g_x[2 * BATCH];
__device__ float g_sldj[BATCH];

// grid-wide barrier: all NB blocks resident by construction
__device__ __forceinline__ void gridbar()
{
    __syncthreads();
    if (threadIdx.x == 0) {
        unsigned old = *(volatile unsigned*)&g_release;
        __threadfence();
        if (atomicAdd(&g_arrive, 1) == NB - 1) {
            atomicExch(&g_arrive, 0);
            __threadfence();
            atomicExch(&g_release, old + 1);
        } else {
            while (*(volatile unsigned*)&g_release == old) __nanosleep(32);
        }
        __threadfence();
    }
    __syncthreads();
}

// shared layout (float offsets)
#define XO_SA    0
#define XO_SC    128
#define XO_STHR  256
#define XO_STHS  384        // persists P1 -> P3
#define XO_SORD  512
#define XO_SVR   640
#define XO_SCANA 768
#define XO_SCANB 900
#define XO_SCNT  1032       // P1 hist ints; P2 reuses as float sN
#define XO_SS1   1164
#define XO_SS2   1296
#define XO_GHBH  1428
#define XO_C2    1684
#define XO_D2    1812
#define XO_TH2R  1940
#define XO_TH2S  2068
#define XO_ORD2  2196
#define XO_SCAN4 2324       // float4[130] (byte off 9296, 16B aligned)
#define XO_RED4  2844       // float4[128] (byte off 11376, 16B aligned)
#define XO_MISC  3356
#define XO_KK2   3360       // float[129*129] padded kinks
#define X_FLOATS 20032
#define SMEM_ALL (X_FLOATS * 4)

__global__ void __launch_bounds__(NT, 1) k_all(
    const float* __restrict__ x,
    const float* __restrict__ v1,  const float* __restrict__ g1,  const float* __restrict__ b1,
    const float* __restrict__ bn1g,const float* __restrict__ bn1b,
    const float* __restrict__ v2,  const float* __restrict__ g2,  const float* __restrict__ b2,
    const float* __restrict__ bn2g,const float* __restrict__ bn2b,
    const float* __restrict__ wf,  const float* __restrict__ bf,
    float* __restrict__ out)
{
    extern __shared__ float X[];
    const int t = threadIdx.x, b = blockIdx.x;
    const int lane = t & 31, wid = t >> 5;

    // ================= P0: copy x, stats of x[:,1] into g_sum[0] =================
    {
        float kS = 0.f, cS = 0.f, kQ = 0.f, cQ = 0.f;
        for (int i = b * NT + t; i < BATCH; i += NB * NT) {
            float2 p = ((const float2*)x)[i];
            __stcg(((float2*)g_x) + i, p);
            float v = p.y;
            { float yk = v - cS; float tk = kS + yk; cS = (tk - kS) - yk; kS = tk; }
            float v2s = v * v;
            { float yk = v2s - cQ; float tk = kQ + yk; cQ = (tk - kQ) - yk; kQ = tk; }
        }
        double s = (double)kS, q = (double)kQ;
        for (int off = 16; off; off >>= 1) {
            s += __shfl_down_sync(0xffffffffu, s, off);
            q += __shfl_down_sync(0xffffffffu, q, off);
        }
        __shared__ double ss[32], sq[32];
        if (!lane) { ss[wid] = s; sq[wid] = q; }
        __syncthreads();
        if (!wid) {
            s = (lane < NT / 32) ? ss[lane] : 0.0;
            q = (lane < NT / 32) ? sq[lane] : 0.0;
            for (int off = 16; off; off >>= 1) {
                s += __shfl_down_sync(0xffffffffu, s, off);
                q += __shfl_down_sync(0xffffffffu, q, off);
            }
            if (!lane) { atomicAdd(&g_sum[0][0], s); atomicAdd(&g_sum[0][1], q); }
        }
        if (b == 1) {   // belt-and-braces: parity-0 stat buffers zero at start
            for (int idx = t; idx < NREP * NSEG; idx += NT) {
                ((int*)g_cntR[0])[idx] = 0;
                ((float*)g_s1R[0])[idx] = 0.f;
                ((float*)g_s2R[0])[idx] = 0.f;
            }
        }
    }
    gridbar();

    for (int l = 0; l < NLAYER; l++) {
        const int par = l & 1, nxt = par ^ 1;
        const int uIdx = (l & 1) ^ 1, oIdx = 1 - uIdx;
        const int isLast = (l == NLAYER - 1);

        float* sa = X + XO_SA; float* sc = X + XO_SC; float* sthr = X + XO_STHR;
        float* sths = X + XO_STHS; int* sord = (int*)(X + XO_SORD); float* svr = X + XO_SVR;
        float* scanA = X + XO_SCANA; float* scanB = X + XO_SCANB;
        int* scnt = (int*)(X + XO_SCNT); float* ss1 = X + XO_SS1; float* ss2 = X + XO_SS2;
        float* miscf = X + XO_MISC;

        // ================= P1: BN1 fold + lvl1 sort + lvl1 table + hist =================
        if (t < H) {
            double mu = __ldcg(&g_sum[par][0]) * (1.0 / BATCH);
            double qq = __ldcg(&g_sum[par][1]) * (1.0 / BATCH);
            double var = qq - mu * mu;
            float meanu = (float)mu;
            float varu = (float)(var < 0.0 ? 0.0 : var);
            float v  = v1[l * H + t];
            float w1 = g1[l * H + t] * (v / fabsf(v));
            float r  = rsqrtf(w1 * w1 * varu + BN_EPS);
            float a  = w1 * bn1g[l * H + t] * r;
            float c  = bn1b[l * H + t] - a * meanu;
            sa[t] = a; sc[t] = c;
            sthr[t] = (a != 0.f) ? (-c / a) : CUDART_INF_F;
        }
        __syncthreads();
        if (t < H) {
            float th = sthr[t];
            int rank = 0;
            for (int j2 = 0; j2 < H; j2++) {
                float tj = sthr[j2];
                rank += (tj < th) || (tj == th && j2 < t);
            }
            sths[rank] = th; sord[rank] = t;
        }
        if (b == NB - 1) {  // zero next-parity buffers + next g_sum
            for (int idx = t; idx < NREP * NSEG; idx += NT) {
                ((int*)g_cntR[nxt])[idx] = 0;
                ((float*)g_s1R[nxt])[idx] = 0.f;
                ((float*)g_s2R[nxt])[idx] = 0.f;
            }
            if (t == 0) { g_sum[nxt][0] = 0.0; g_sum[nxt][1] = 0.0; }
        }
        __syncthreads();

        if (b < H) {  // build level-1 column j=b
            const int j = b;
            if (t < H) svr[t] = v2[l * H * H + j * H + t];
            __syncthreads();
            if (t == 0) {
                float nrm = 0.f;
                for (int tt = 0; tt < H; tt++) nrm = fmaf(svr[tt], svr[tt], nrm);
                miscf[0] = g2[l * H + j] / sqrtf(nrm);
            }
            __syncthreads();
            float wsc = miscf[0];
            float* redA = (float*)(X + XO_RED4);
            float* redB = redA + 128;
            if (t < H) {
                float aa = sa[t], cc = sc[t], w = wsc * svr[t];
                redA[t] = (aa < 0.f) ? w * aa : 0.f;
                redB[t] = (aa < 0.f) ? w * cc : ((aa == 0.f && cc > 0.f) ? w * cc : 0.f);
            }
            if (t >= 1 && t <= H) {
                int kk = sord[t - 1];
                float aa = sa[kk], cc = sc[kk], w = wsc * svr[kk];
                float sgn = (aa > 0.f) ? 1.f : ((aa < 0.f) ? -1.f : 0.f);
                scanA[t] = sgn * w * aa;
                scanB[t] = sgn * w * cc;
            }
            if (t == 0) { scanA[0] = 0.f; scanB[0] = 0.f; }
            __syncthreads();
            if (t == 0) {
                float A0 = 0.f, B0 = b2[l * H + j];
                for (int tt = 0; tt < H; tt++) { A0 += redA[tt]; B0 += redB[tt]; }
                miscf[1] = A0; miscf[2] = B0;
            }
            for (int off = 1; off <= H; off <<= 1) {
                float aadd = 0.f, badd = 0.f;
                if (t >= off && t <= H) { aadd = scanA[t - off]; badd = scanB[t - off]; }
                __syncthreads();
                if (t >= off && t <= H) { scanA[t] += aadd; scanB[t] += badd; }
                __syncthreads();
            }
            if (t <= H) {
                float2 val = make_float2(miscf[1] + scanA[t], miscf[2] + scanB[t]);
                __stcg(((float2*)g_tab) + t * H + j, val);
            }
        }
        __syncthreads();

        // hist (no mseg store)
        for (int i = t; i < NSEG; i += NT) { scnt[i] = 0; ss1[i] = 0.f; ss2[i] = 0.f; }
        __syncthreads();
        for (int i = b * NT + t; i < BATCH; i += NB * NT) {
            float2 p = __ldcg(((const float2*)g_x) + i);
            float u = uIdx ? p.y : p.x;
            int m = 0;
#pragma unroll
            for (int s = 64; s >= 1; s >>= 1) { int nm = m + s; if (sths[nm - 1] < u) m = nm; }
            if (sths[H - 1] < u) m = H;

            bool lo = (m == 0), hi = (m == H);
            float u2 = u * u;
            float s1l = lo ? u : 0.f, s2l = lo ? u2 : 0.f;
            float s1h = hi ? u : 0.f, s2h = hi ? u2 : 0.f;
#pragma unroll
            for (int off = 16; off; off >>= 1) {
                s1l += __shfl_xor_sync(0xffffffffu, s1l, off);
                s2l += __shfl_xor_sync(0xffffffffu, s2l, off);
                s1h += __shfl_xor_sync(0xffffffffu, s1h, off);
                s2h += __shfl_xor_sync(0xffffffffu, s2h, off);
            }
            unsigned blo = __ballot_sync(0xffffffffu, lo);
            unsigned bhi = __ballot_sync(0xffffffffu, hi);
            if (lane == 0) {
                if (blo) { atomicAdd(&scnt[0], (int)__popc(blo)); atomicAdd(&ss1[0], s1l); atomicAdd(&ss2[0], s2l); }
                if (bhi) { atomicAdd(&scnt[H], (int)__popc(bhi)); atomicAdd(&ss1[H], s1h); atomicAdd(&ss2[H], s2h); }
            }
            if (!lo && !hi) {
                atomicAdd(&scnt[m], 1);
                atomicAdd(&ss1[m], u);
                atomicAdd(&ss2[m], u2);
            }
        }
        __syncthreads();
        {
            int r = b & (NREP - 1);
            for (int i = t; i < NSEG; i += NT) {
                if (scnt[i]) {
                    atomicAdd(&g_cntR[par][r][i], scnt[i]);
                    atomicAdd(&g_s1R[par][r][i], ss1[i]);
                    atomicAdd(&g_s2R[par][r][i], ss2[i]);
                }
            }
        }
        gridbar();

        // ================= P2: BN2 fold + level-2 table (block b = segment m) =================
        if (b <= H) {
            const int m = b;
            float* sN  = X + XO_SCNT;   // reuse as float
            float* s1v = X + XO_SS1;
            float* s2v = X + XO_SS2;
            float* ghbhS = X + XO_GHBH;
            float* c2 = X + XO_C2; float* d2 = X + XO_D2;
            float* th2r = X + XO_TH2R; float* th2s = X + XO_TH2S;
            int* ord2 = (int*)(X + XO_ORD2);
            float4* scan4 = (float4*)(X + XO_SCAN4);
            float4* red4  = (float4*)(X + XO_RED4);

            if (t < NSEG) {
                int c = 0; float a = 0.f, bb = 0.f;
#pragma unroll
                for (int r = 0; r < NREP; r++) {
                    c  += __ldcg(&g_cntR[par][r][t]);
                    a  += __ldcg(&g_s1R[par][r][t]);
                    bb += __ldcg(&g_s2R[par][r][t]);
                }
                sN[t] = (float)c; s1v[t] = a; s2v[t] = bb;
            }
            __syncthreads();
            if (t < H) {   // ghbh_j, Kahan fp32
                float a1 = 0.f, c1 = 0.f, a2 = 0.f, c2k = 0.f;
                for (int mm = 0; mm < NSEG; mm++) {
                    float2 ab = __ldcg(((const float2*)g_tab) + mm * H + t);
                    float N = sN[mm], S1 = s1v[mm], S2 = s2v[mm];
                    float t1 = ab.x * S1 + ab.y * N;
                    float t2 = ab.x * (ab.x * S2 + 2.f * ab.y * S1) + ab.y * ab.y * N;
                    { float yk = t1 - c1; float tk = a1 + yk; c1 = (tk - a1) - yk; a1 = tk; }
                    { float yk = t2 - c2k; float tk = a2 + yk; c2k = (tk - a2) - yk; a2 = tk; }
                }
                float mean = a1 * (1.f / BATCH);
                float var  = a2 * (1.f / BATCH) - mean * mean;
                if (var < 0.f) var = 0.f;
                float gh = bn2g[l * H + t] * rsqrtf(var + BN_EPS);
                float bh = bn2b[l * H + t] - gh * mean;
                ghbhS[2 * t] = gh; ghbhS[2 * t + 1] = bh;
            }
            __syncthreads();
            if (t < H) {
                float2 ab = __ldcg(((const float2*)g_tab) + m * H + t);
                float gh = ghbhS[2 * t], bh = ghbhS[2 * t + 1];
                float c = gh * ab.x;
                float d = fmaf(gh, ab.y, bh);
                c2[t] = c; d2[t] = d;
                th2r[t] = (c != 0.f) ? (-d / c) : CUDART_INF_F;
            }
            __syncthreads();
            if (t < H) {
                float th = th2r[t];
                int rank = 0;
                for (int j2 = 0; j2 < H; j2++) {
                    float tj = th2r[j2];
                    rank += (tj < th) || (tj == th && j2 < t);
                }
                th2s[rank] = th; ord2[rank] = t;
            }
            // base terms
            if (t < H) {
                float c = c2[t], d = d2[t];
                float w0 = wf[(l * 2 + 0) * H + t], w1 = wf[(l * 2 + 1) * H + t];
                bool act = (c < 0.f) || (c == 0.f && d > 0.f);
                float4 bt;
                bt.x = (c < 0.f) ? w0 * c : 0.f;
                bt.z = (c < 0.f) ? w1 * c : 0.f;
                bt.y = act ? w0 * d : 0.f;
                bt.w = act ? w1 * d : 0.f;
                red4[t] = bt;
            }
            __syncthreads();
            for (int off = 64; off; off >>= 1) {
                if (t < off) {
                    float4 a4 = red4[t], b4 = red4[t + off];
                    red4[t] = make_float4(a4.x + b4.x, a4.y + b4.y, a4.z + b4.z, a4.w + b4.w);
                }
                __syncthreads();
            }
            // scan deltas
            if (t >= 1 && t <= H) {
                int j = ord2[t - 1];
                float c = c2[j], d = d2[j];
                float w0 = wf[(l * 2 + 0) * H + j], w1 = wf[(l * 2 + 1) * H + j];
                float sgn = (c > 0.f) ? 1.f : ((c < 0.f) ? -1.f : 0.f);
                scan4[t] = make_float4(sgn * w0 * c, sgn * w0 * d, sgn * w1 * c, sgn * w1 * d);
            }
            if (t == 0) scan4[0] = make_float4(0.f, 0.f, 0.f, 0.f);
            __syncthreads();
            for (int off = 1; off <= H; off <<= 1) {
                float4 add = make_float4(0.f, 0.f, 0.f, 0.f);
                if (t >= off && t <= H) add = scan4[t - off];
                __syncthreads();
                if (t >= off && t <= H) {
                    float4 s4 = scan4[t];
                    scan4[t] = make_float4(s4.x + add.x, s4.y + add.y, s4.z + add.z, s4.w + add.w);
                }
                __syncthreads();
            }
            if (t < H) __stcg(&g_kink2[m * H + t], th2s[t]);
            if (t <= H) {
                float bf0 = bf[l * 2], bf1 = bf[l * 2 + 1];
                float4 b4 = red4[0], s4 = scan4[t];
                float4 ef = make_float4(b4.x + s4.x, b4.y + s4.y + bf0,
                                        b4.z + s4.z, b4.w + s4.w + bf1);
                __stcg(&g_EF[m * NSEG + t], ef);
            }
        }
        gridbar();

        // ================= P3: apply (coalesced, no sort) =================
        {
            float* kk2 = X + XO_KK2;   // padded [m*129 + r]
            for (int idx = t; idx < NSEG * H; idx += NT) {
                int m = idx >> 7, r = idx & 127;
                kk2[m * 129 + r] = __ldcg(&g_kink2[idx]);
            }
            __syncthreads();

            float kS = 0.f, cS = 0.f, kQ = 0.f, cQ = 0.f;
            for (int i = b * NT + t; i < BATCH; i += NB * NT) {
                float2 p = __ldcg(((const float2*)g_x) + i);
                float u  = uIdx ? p.y : p.x;
                float xo = uIdx ? p.x : p.y;
                // level-1 search
                int m = 0;
#pragma unroll
                for (int s = 64; s >= 1; s >>= 1) { int nm = m + s; if (sths[nm - 1] < u) m = nm; }
                if (sths[H - 1] < u) m = H;
                // level-2 search
                const float* kr = kk2 + m * 129;
                int r = 0;
#pragma unroll
                for (int s = 64; s >= 1; s >>= 1) { int nr = r + s; if (kr[nr - 1] < u) r = nr; }
                if (kr[H - 1] < u) r = H;

                float4 ef = __ldcg(&g_EF[m * NSEG + r]);
                float st0 = fmaf(ef.x, u, ef.y);
                float st1 = fmaf(ef.z, u, ef.w);
                float e2  = __expf(2.f * st0);
                float sv  = 1.f - 2.f * __fdividef(1.f, e2 + 1.f);   // tanh
                float y   = fmaf(__expf(sv), xo, st1);
                float sld = (l == 0 ? 0.f : __ldcg(&g_sldj[i])) + sv;

                if (!isLast) {
                    __stcg(&g_x[2 * i + oIdx], y);
                    __stcg(&g_sldj[i], sld);
                    { float yk = y - cS;  float tk = kS + yk; cS = (tk - kS) - yk; kS = tk; }
                    float yy = y * y;
                    { float yk = yy - cQ; float tk = kQ + yk; cQ = (tk - kQ) - yk; kQ = tk; }
                } else {
                    float zu = __fdividef(1.f, 1.f + __expf(-u));
                    float zo = __fdividef(1.f, 1.f + __expf(-y));
                    sld += __logf(zu * (1.f - zu) + FLOW_EPS) + __logf(zo * (1.f - zo) + FLOW_EPS);
                    out[2 * i + uIdx] = zu;
                    out[2 * i + oIdx] = zo;
                    out[2 * BATCH + i] = sld;
                }
            }

            if (!isLast) {
                double s = (double)kS, q = (double)kQ;
                for (int off = 16; off; off >>= 1) {
                    s += __shfl_down_sync(0xffffffffu, s, off);
                    q += __shfl_down_sync(0xffffffffu, q, off);
                }
                __shared__ double rs[32], rq[32];
                if (!lane) { rs[wid] = s; rq[wid] = q; }
                __syncthreads();
                if (!wid) {
                    s = (lane < NT / 32) ? rs[lane] : 0.0;
                    q = (lane < NT / 32) ? rq[lane] : 0.0;
                    for (int off = 16; off; off >>= 1) {
                        s += __shfl_down_sync(0xffffffffu, s, off);
                        q += __shfl_down_sync(0xffffffffu, q, off);
                    }
                    if (!lane) { atomicAdd(&g_sum[nxt][0], s); atomicAdd(&g_sum[nxt][1], q); }
                }
            }
        }
        if (!isLast) gridbar();
    }
}

// ---------------- host launcher ----------------
extern "C" void kernel_launch(void* const* d_in, const int* in_sizes, int n_in,
                              void* d_out, int out_size)
{
    const float* x    = (const float*)d_in[0];
    const float* v1   = (const float*)d_in[1];
    const float* g1   = (const float*)d_in[2];
    const float* b1   = (const float*)d_in[3];
    const float* bn1g = (const float*)d_in[4];
    const float* bn1b = (const float*)d_in[5];
    const float* v2   = (const float*)d_in[6];
    const float* g2   = (const float*)d_in[7];
    const float* b2   = (const float*)d_in[8];
    const float* bn2g = (const float*)d_in[9];
    const float* bn2b = (const float*)d_in[10];
    const float* wf   = (const float*)d_in[11];
    const float* bf   = (const float*)d_in[12];
    float* out = (float*)d_out;

    cudaFuncSetAttribute(k_all, cudaFuncAttributeMaxDynamicSharedMemorySize, SMEM_ALL);
    k_all<<<NB, NT, SMEM_ALL>>>(x, v1, g1, b1, bn1g, bn1b, v2, g2, b2,
                                bn2g, bn2b, wf, bf, out);
    (void)in_sizes; (void)n_in; (void)out_size;
}